// round 2
// baseline (speedup 1.0000x reference)
#include <cuda_runtime.h>
#include <cuda_bf16.h>

// Problem constants (B,H,N,D,K2) = (4,8,4096,64,16)
// FFT length 2N = 8192 real  -> packed 4096-point complex FFT.
#define THREADS 512

// Filter spectrum scratch: Ahat[h][d][f], f = 0..4096 natural order. 16.8 MB.
__device__ float2 g_Ahat[8 * 64 * 4097];

__device__ __forceinline__ float2 cmul(float2 a, float2 b) {
    return make_float2(a.x * b.x - a.y * b.y, a.x * b.y + a.y * b.x);
}
__device__ __forceinline__ float4 f4add(float4 a, float4 b) {
    return make_float4(a.x + b.x, a.y + b.y, a.z + b.z, a.w + b.w);
}
__device__ __forceinline__ float4 f4sub(float4 a, float4 b) {
    return make_float4(a.x - b.x, a.y - b.y, a.z - b.z, a.w - b.w);
}
// multiply both packed complexes by -i : (x+iy)*(-i) = y - ix
__device__ __forceinline__ float4 f4mulni(float4 v) {
    return make_float4(v.y, -v.x, v.w, -v.z);
}
// multiply both packed complexes by +i
__device__ __forceinline__ float4 f4muli(float4 v) {
    return make_float4(-v.y, v.x, -v.w, v.z);
}
// multiply both packed complexes by scalar complex w
__device__ __forceinline__ float4 f4cmul(float4 v, float2 w) {
    return make_float4(v.x * w.x - v.y * w.y, v.x * w.y + v.y * w.x,
                       v.z * w.x - v.w * w.y, v.z * w.y + v.w * w.x);
}
// reverse 6 base-4 digits of a 12-bit value (digit reversal = bit-reverse 12 bits, then swap bit pairs)
__device__ __forceinline__ int rev4_12(int v) {
    unsigned r = __brev((unsigned)v) >> 20;
    return (int)(((r & 0x555u) << 1) | ((r & 0xAAAu) >> 1));
}

// ---------------------------------------------------------------------------
// In-place radix-4 DIF forward FFT, 4096 points, natural input -> base-4
// digit-reversed output. Two independent sequences packed per float4
// (d0 in .xy, d1 in .zw) sharing twiddles.
// ---------------------------------------------------------------------------
__device__ void fft4_fwd(float4* s, int tid) {
#pragma unroll
    for (int lq = 10; lq >= 0; lq -= 2) {
        int q = 1 << lq;
        float Linv = 1.0f / (float)(q << 2);
#pragma unroll
        for (int it = 0; it < 2; ++it) {
            int m = tid + (it << 9);           // butterfly index 0..1023
            int j = m & (q - 1);
            int base = ((m >> lq) << (lq + 2)) | j;
            float4 a = s[base];
            float4 b = s[base + q];
            float4 c = s[base + 2 * q];
            float4 d = s[base + 3 * q];
            float4 t0 = f4add(a, c), t1 = f4sub(a, c);
            float4 t2 = f4add(b, d), t3 = f4mulni(f4sub(b, d));
            float ang = -6.28318530717958647692f * (float)j * Linv;
            float sn, cs;
            __sincosf(ang, &sn, &cs);
            float2 w1 = make_float2(cs, sn);
            float2 w2 = cmul(w1, w1);
            float2 w3 = cmul(w2, w1);
            s[base]         = f4add(t0, t2);
            s[base + q]     = f4cmul(f4add(t1, t3), w1);
            s[base + 2 * q] = f4cmul(f4sub(t0, t2), w2);
            s[base + 3 * q] = f4cmul(f4sub(t1, t3), w3);
        }
        __syncthreads();
    }
}

// Exact mirror inverse (unnormalized): digit-reversed input -> natural output.
// Overall scale 1/4096 is folded into the frequency-domain middle step.
__device__ void fft4_inv(float4* s, int tid) {
#pragma unroll
    for (int lq = 0; lq <= 10; lq += 2) {
        int q = 1 << lq;
        float Linv = 1.0f / (float)(q << 2);
#pragma unroll
        for (int it = 0; it < 2; ++it) {
            int m = tid + (it << 9);
            int j = m & (q - 1);
            int base = ((m >> lq) << (lq + 2)) | j;
            float4 y0 = s[base];
            float4 y1 = s[base + q];
            float4 y2 = s[base + 2 * q];
            float4 y3 = s[base + 3 * q];
            float ang = 6.28318530717958647692f * (float)j * Linv;  // conj twiddles
            float sn, cs;
            __sincosf(ang, &sn, &cs);
            float2 w1 = make_float2(cs, sn);
            float2 w2 = cmul(w1, w1);
            float2 w3 = cmul(w2, w1);
            float4 u1 = f4cmul(y1, w1);
            float4 u2 = f4cmul(y2, w2);
            float4 u3 = f4cmul(y3, w3);
            float4 p  = f4add(y0, u2), qq = f4sub(y0, u2);
            float4 r  = f4add(u1, u3), t  = f4muli(f4sub(u1, u3));
            s[base]         = f4add(p, r);
            s[base + q]     = f4add(qq, t);
            s[base + 2 * q] = f4sub(p, r);
            s[base + 3 * q] = f4sub(qq, t);
        }
        __syncthreads();
    }
}

// Frequency-domain step for one channel: unpack packed-real spectrum pair
// (Z[f], Z[4096-f]) -> X[f], X[4096-f] of the 8192-pt real FFT, multiply by
// Ahat, repack into Z'[f], Z'[4096-f] for the packed inverse. Scale by invN.
__device__ __forceinline__ void mid_pair(float2 Zf, float2 Zg, float2 Af, float2 Ag,
                                         float2 W, float invN,
                                         float2* zf_out, float2* zg_out) {
    // E[f] = (Z[f] + conj(Z[-f]))/2 ; O[f] = -i/2 (Z[f] - conj(Z[-f]))
    float2 E  = make_float2(0.5f * (Zf.x + Zg.x), 0.5f * (Zf.y - Zg.y));
    float2 O  = make_float2(0.5f * (Zf.y + Zg.y), -0.5f * (Zf.x - Zg.x));
    float2 WO = cmul(W, O);
    float2 Xf  = make_float2(E.x + WO.x, E.y + WO.y);   // X[f]
    float2 Xgc = make_float2(E.x - WO.x, E.y - WO.y);   // conj(X[4096-f])
    float2 Pf = cmul(Xf, Af);
    float2 Pg = cmul(make_float2(Xgc.x, -Xgc.y), Ag);
    // Z'[f] = ((Pf + conj Pg) + i*conj(W)*(Pf - conj Pg)) / 2 ;  i*conj(W) = (W.y, W.x)
    float2 S  = make_float2(Pf.x + Pg.x, Pf.y - Pg.y);
    float2 Dd = make_float2(Pf.x - Pg.x, Pf.y + Pg.y);
    float2 T1 = cmul(make_float2(W.y, W.x), Dd);
    *zf_out = make_float2(0.5f * invN * (S.x + T1.x), 0.5f * invN * (S.y + T1.y));
    // Z'[g] = ((Pg + conj Pf) - i*W*(Pg - conj Pf)) / 2 ;  -i*W = (W.y, -W.x)
    float2 S2 = make_float2(Pg.x + Pf.x, Pg.y - Pf.y);
    float2 D2 = make_float2(Pg.x - Pf.x, Pg.y + Pf.y);
    float2 T2 = cmul(make_float2(W.y, -W.x), D2);
    *zg_out = make_float2(0.5f * invN * (S2.x + T2.x), 0.5f * invN * (S2.y + T2.y));
}

// ---------------------------------------------------------------------------
// K0: build filter spectrum Ahat[h][d][0..4096] (natural order).
// grid = (32 d-pairs, 8 heads). a[t] = decay[t] * sum_k coef[h,k,d]*cos[t,k].
// ---------------------------------------------------------------------------
__global__ void __launch_bounds__(THREADS)
k_filter(const float* __restrict__ decay, const float* __restrict__ cosv,
         const float* __restrict__ coef) {
    extern __shared__ float4 s[];
    int tid = threadIdx.x;
    int d0 = blockIdx.x * 2;
    int h  = blockIdx.y;

    float cf0[16], cf1[16];
#pragma unroll
    for (int k = 0; k < 16; ++k) {
        cf0[k] = coef[(h * 16 + k) * 64 + d0];
        cf1[k] = coef[(h * 16 + k) * 64 + d0 + 1];
    }
    // pack: s[t] = (a_d0[2t], a_d0[2t+1], a_d1[2t], a_d1[2t+1])
    for (int t = tid; t < 4096; t += THREADS) {
        int t0 = 2 * t, t1 = 2 * t + 1;
        float a00 = 0.f, a10 = 0.f, a01 = 0.f, a11 = 0.f;
#pragma unroll
        for (int k = 0; k < 16; ++k) {
            float c0 = cosv[t0 * 16 + k];
            float c1 = cosv[t1 * 16 + k];
            a00 += cf0[k] * c0;  a01 += cf1[k] * c0;
            a10 += cf0[k] * c1;  a11 += cf1[k] * c1;
        }
        float de0 = decay[t0], de1 = decay[t1];
        s[t] = make_float4(a00 * de0, a10 * de1, a01 * de0, a11 * de1);
    }
    __syncthreads();
    fft4_fwd(s, tid);

    float2* A0 = g_Ahat + (size_t)(h * 64 + d0) * 4097;
    float2* A1 = A0 + 4097;
    for (int f = tid; f <= 2048; f += THREADS) {
        int g = 4096 - f;
        float4 Zf = s[rev4_12(f & 4095)];
        float4 Zg = s[rev4_12(g & 4095)];
        float ang = -3.14159265358979323846f * (float)f * (1.0f / 4096.0f);
        float sn, cs;
        __sincosf(ang, &sn, &cs);
        float2 W = make_float2(cs, sn);
        // channel d0 (.xy)
        {
            float2 zf = make_float2(Zf.x, Zf.y), zg = make_float2(Zg.x, Zg.y);
            float2 E  = make_float2(0.5f * (zf.x + zg.x), 0.5f * (zf.y - zg.y));
            float2 O  = make_float2(0.5f * (zf.y + zg.y), -0.5f * (zf.x - zg.x));
            float2 WO = cmul(W, O);
            A0[f] = make_float2(E.x + WO.x, E.y + WO.y);          // X[f]
            A0[g] = make_float2(E.x - WO.x, -(E.y - WO.y));       // X[g] = conj(E - W*O)
        }
        // channel d0+1 (.zw)
        {
            float2 zf = make_float2(Zf.z, Zf.w), zg = make_float2(Zg.z, Zg.w);
            float2 E  = make_float2(0.5f * (zf.x + zg.x), 0.5f * (zf.y - zg.y));
            float2 O  = make_float2(0.5f * (zf.y + zg.y), -0.5f * (zf.x - zg.x));
            float2 WO = cmul(W, O);
            A1[f] = make_float2(E.x + WO.x, E.y + WO.y);
            A1[g] = make_float2(E.x - WO.x, -(E.y - WO.y));
        }
    }
}

// ---------------------------------------------------------------------------
// K1: per (b,h,d-pair): pack x -> FFT -> multiply by Ahat -> IFFT -> first N.
// grid = (32 d-pairs, 32 bh).
// ---------------------------------------------------------------------------
__global__ void __launch_bounds__(THREADS)
k_conv(const float* __restrict__ x, float* __restrict__ out) {
    extern __shared__ float4 s[];
    int tid = threadIdx.x;
    int d0 = blockIdx.x * 2;
    int bh = blockIdx.y;           // b*8 + h
    int h  = bh & 7;

    const float* xb = x + (size_t)bh * 4096 * 64 + d0;
    for (int t = tid; t < 4096; t += THREADS) {
        float4 v = make_float4(0.f, 0.f, 0.f, 0.f);
        if (t < 2048) {
            float2 A = *reinterpret_cast<const float2*>(xb + (size_t)(2 * t) * 64);
            float2 B = *reinterpret_cast<const float2*>(xb + (size_t)(2 * t + 1) * 64);
            v = make_float4(A.x, B.x, A.y, B.y);
        }
        s[t] = v;
    }
    __syncthreads();
    fft4_fwd(s, tid);

    const float2* A0 = g_Ahat + (size_t)(h * 64 + d0) * 4097;
    const float2* A1 = A0 + 4097;
    const float invN = 1.0f / 4096.0f;
    for (int f = tid; f <= 2048; f += THREADS) {
        int g = 4096 - f;
        int pf = rev4_12(f & 4095);
        int pg = rev4_12(g & 4095);
        float4 Zf = s[pf];
        float4 Zg = s[pg];
        float ang = -3.14159265358979323846f * (float)f * (1.0f / 4096.0f);
        float sn, cs;
        __sincosf(ang, &sn, &cs);
        float2 W = make_float2(cs, sn);
        float2 zpf0, zpg0, zpf1, zpg1;
        mid_pair(make_float2(Zf.x, Zf.y), make_float2(Zg.x, Zg.y), A0[f], A0[g], W, invN, &zpf0, &zpg0);
        mid_pair(make_float2(Zf.z, Zf.w), make_float2(Zg.z, Zg.w), A1[f], A1[g], W, invN, &zpf1, &zpg1);
        s[pf] = make_float4(zpf0.x, zpf0.y, zpf1.x, zpf1.y);
        if (f != 0)   // f==0 has no Z'[4096] slot; Z'[0] fully handled by zf
            s[pg] = make_float4(zpg0.x, zpg0.y, zpg1.x, zpg1.y);
    }
    __syncthreads();
    fft4_inv(s, tid);

    // z'[t] = (out_d0[2t] + i out_d0[2t+1], out_d1[2t] + i out_d1[2t+1]); keep first N=4096 samples.
    float* ob = out + (size_t)bh * 4096 * 64 + d0;
    for (int t = tid; t < 2048; t += THREADS) {
        float4 v = s[t];
        *reinterpret_cast<float2*>(ob + (size_t)(2 * t) * 64)     = make_float2(v.x, v.z);
        *reinterpret_cast<float2*>(ob + (size_t)(2 * t + 1) * 64) = make_float2(v.y, v.w);
    }
}

extern "C" void kernel_launch(void* const* d_in, const int* in_sizes, int n_in,
                              void* d_out, int out_size) {
    const float* x     = (const float*)d_in[0];
    const float* decay = (const float*)d_in[1];
    const float* cosv  = (const float*)d_in[2];
    const float* coef  = (const float*)d_in[3];
    // d_in[4] = index (arange(N)) -- identity gather of the first N samples.
    float* out = (float*)d_out;

    cudaFuncSetAttribute(k_filter, cudaFuncAttributeMaxDynamicSharedMemorySize, 65536);
    cudaFuncSetAttribute(k_conv,   cudaFuncAttributeMaxDynamicSharedMemorySize, 65536);

    k_filter<<<dim3(32, 8),  THREADS, 65536>>>(decay, cosv, coef);
    k_conv  <<<dim3(32, 32), THREADS, 65536>>>(x, out);
}

// round 3
// speedup vs baseline: 2.7034x; 2.7034x over previous
#include <cuda_runtime.h>
#include <cuda_bf16.h>

// (B,H,N,D,K2) = (4,8,4096,64,16); FFT length 2N=8192 real -> packed 4096-pt complex FFT.
#define THREADS 256
// XOR bank swizzle on float4 indices: makes every FFT stage (q=512/64/8/1),
// the pack/mid/output loops all LDS.128-conflict-free.
#define SW(i) ((i) ^ (((i) >> 3) & 7))

// Packed time-domain filter a: g_pa[(h*32+dp)*4096 + tt] = (a0[2tt],a0[2tt+1],a1[2tt],a1[2tt+1])
__device__ float4 g_pa[256 * 4096];
// Filter spectrum in digit-reversed order, packed 2 channels per float4:
// g_Af[off+p] = A[rev8(p)], g_Ag[off+p] = A[4096 - rev8(p)]  (full 8192-pt DFT values)
__device__ float4 g_Af[256 * 4096];
__device__ float4 g_Ag[256 * 4096];

__device__ __forceinline__ float2 cmul(float2 a, float2 b) {
    return make_float2(a.x * b.x - a.y * b.y, a.x * b.y + a.y * b.x);
}
__device__ __forceinline__ float4 f4add(float4 a, float4 b) {
    return make_float4(a.x + b.x, a.y + b.y, a.z + b.z, a.w + b.w);
}
__device__ __forceinline__ float4 f4sub(float4 a, float4 b) {
    return make_float4(a.x - b.x, a.y - b.y, a.z - b.z, a.w - b.w);
}
__device__ __forceinline__ float4 f4mulni(float4 v) {   // * (-i)
    return make_float4(v.y, -v.x, v.w, -v.z);
}
__device__ __forceinline__ float4 f4muli(float4 v) {    // * (+i)
    return make_float4(-v.y, v.x, -v.w, v.z);
}
__device__ __forceinline__ float4 f4cmul(float4 v, float2 w) {
    return make_float4(v.x * w.x - v.y * w.y, v.x * w.y + v.y * w.x,
                       v.z * w.x - v.w * w.y, v.z * w.y + v.w * w.x);
}
// reverse 4 octal digits of a 12-bit value
__device__ __forceinline__ int rev8_12(int v) {
    return ((v & 7) << 9) | (((v >> 3) & 7) << 6) | (((v >> 6) & 7) << 3) | ((v >> 9) & 7);
}

// ---------------- radix-8 butterflies (two packed channels per float4) -----
__device__ __forceinline__ void dft8_fwd(float4* x) {
    const float C = 0.70710678118654752440f;
    float4 u0 = f4add(x[0], x[4]), u1 = f4add(x[1], x[5]);
    float4 u2 = f4add(x[2], x[6]), u3 = f4add(x[3], x[7]);
    float4 v0 = f4sub(x[0], x[4]), v1 = f4sub(x[1], x[5]);
    float4 v2 = f4sub(x[2], x[6]), v3 = f4sub(x[3], x[7]);
    float4 a0 = f4add(u0, u2), a1 = f4sub(u0, u2);
    float4 a2 = f4add(u1, u3), a3 = f4mulni(f4sub(u1, u3));
    float4 z1 = make_float4(C * (v1.x + v1.y), C * (v1.y - v1.x),
                            C * (v1.z + v1.w), C * (v1.w - v1.z));      // * e^{-i pi/4}
    float4 z2 = f4mulni(v2);
    float4 z3 = make_float4(C * (v3.y - v3.x), -C * (v3.x + v3.y),
                            C * (v3.w - v3.z), -C * (v3.z + v3.w));     // * e^{-3i pi/4}
    float4 b0 = f4add(v0, z2), b1 = f4sub(v0, z2);
    float4 b2 = f4add(z1, z3), b3 = f4mulni(f4sub(z1, z3));
    x[0] = f4add(a0, a2); x[2] = f4add(a1, a3);
    x[4] = f4sub(a0, a2); x[6] = f4sub(a1, a3);
    x[1] = f4add(b0, b2); x[3] = f4add(b1, b3);
    x[5] = f4sub(b0, b2); x[7] = f4sub(b1, b3);
}
__device__ __forceinline__ void dft8_inv(float4* x) {
    const float C = 0.70710678118654752440f;
    float4 u0 = f4add(x[0], x[4]), u1 = f4add(x[1], x[5]);
    float4 u2 = f4add(x[2], x[6]), u3 = f4add(x[3], x[7]);
    float4 v0 = f4sub(x[0], x[4]), v1 = f4sub(x[1], x[5]);
    float4 v2 = f4sub(x[2], x[6]), v3 = f4sub(x[3], x[7]);
    float4 a0 = f4add(u0, u2), a1 = f4sub(u0, u2);
    float4 a2 = f4add(u1, u3), a3 = f4muli(f4sub(u1, u3));
    float4 z1 = make_float4(C * (v1.x - v1.y), C * (v1.x + v1.y),
                            C * (v1.z - v1.w), C * (v1.z + v1.w));      // * e^{+i pi/4}
    float4 z2 = f4muli(v2);
    float4 z3 = make_float4(-C * (v3.x + v3.y), C * (v3.x - v3.y),
                            -C * (v3.z + v3.w), C * (v3.z - v3.w));     // * e^{+3i pi/4}
    float4 b0 = f4add(v0, z2), b1 = f4sub(v0, z2);
    float4 b2 = f4add(z1, z3), b3 = f4muli(f4sub(z1, z3));
    x[0] = f4add(a0, a2); x[2] = f4add(a1, a3);
    x[4] = f4sub(a0, a2); x[6] = f4sub(a1, a3);
    x[1] = f4add(b0, b2); x[3] = f4add(b1, b3);
    x[5] = f4sub(b0, b2); x[7] = f4sub(b1, b3);
}

// ---------------- 4096-pt radix-8 FFTs, 4 smem rounds, swizzled ------------
// fwd: natural input -> octal-digit-reversed output (stored[p] = Z[rev8(p)])
__device__ void fft8_fwd(float4* s, int tid) {
#pragma unroll
    for (int lq = 9; lq >= 0; lq -= 3) {
        const int q = 1 << lq;
#pragma unroll
        for (int it = 0; it < 2; ++it) {
            int m = tid + (it << 8);
            int j = m & (q - 1);
            int base = ((m >> lq) << (lq + 3)) | j;
            float4 x[8];
#pragma unroll
            for (int k = 0; k < 8; ++k) x[k] = s[SW(base + k * q)];
            dft8_fwd(x);
            if (lq > 0) {
                float ang = -6.28318530717958647692f * (float)j / (float)(q << 3);
                float sn, cs; __sincosf(ang, &sn, &cs);
                float2 t1 = make_float2(cs, sn);
                float2 t2 = cmul(t1, t1), t3 = cmul(t2, t1), t4 = cmul(t2, t2);
                float2 t5 = cmul(t4, t1), t6 = cmul(t4, t2), t7 = cmul(t4, t3);
                x[1] = f4cmul(x[1], t1); x[2] = f4cmul(x[2], t2); x[3] = f4cmul(x[3], t3);
                x[4] = f4cmul(x[4], t4); x[5] = f4cmul(x[5], t5);
                x[6] = f4cmul(x[6], t6); x[7] = f4cmul(x[7], t7);
            }
#pragma unroll
            for (int k = 0; k < 8; ++k) s[SW(base + k * q)] = x[k];
        }
        __syncthreads();
    }
}
// exact mirror inverse (unnormalized): digit-reversed input -> natural output
__device__ void fft8_inv(float4* s, int tid) {
#pragma unroll
    for (int lq = 0; lq <= 9; lq += 3) {
        const int q = 1 << lq;
#pragma unroll
        for (int it = 0; it < 2; ++it) {
            int m = tid + (it << 8);
            int j = m & (q - 1);
            int base = ((m >> lq) << (lq + 3)) | j;
            float4 x[8];
#pragma unroll
            for (int k = 0; k < 8; ++k) x[k] = s[SW(base + k * q)];
            if (lq > 0) {
                float ang = 6.28318530717958647692f * (float)j / (float)(q << 3);
                float sn, cs; __sincosf(ang, &sn, &cs);
                float2 t1 = make_float2(cs, sn);
                float2 t2 = cmul(t1, t1), t3 = cmul(t2, t1), t4 = cmul(t2, t2);
                float2 t5 = cmul(t4, t1), t6 = cmul(t4, t2), t7 = cmul(t4, t3);
                x[1] = f4cmul(x[1], t1); x[2] = f4cmul(x[2], t2); x[3] = f4cmul(x[3], t3);
                x[4] = f4cmul(x[4], t4); x[5] = f4cmul(x[5], t5);
                x[6] = f4cmul(x[6], t6); x[7] = f4cmul(x[7], t7);
            }
            dft8_inv(x);
#pragma unroll
            for (int k = 0; k < 8; ++k) s[SW(base + k * q)] = x[k];
        }
        __syncthreads();
    }
}

// Frequency-domain step for one channel: unpack packed-real pair, multiply by
// filter spectrum, repack. Returns Z'[f] and Z'[4096-f], scaled by invN.
__device__ __forceinline__ void mid_pair(float2 Zf, float2 Zg, float2 Af, float2 Ag,
                                         float2 W, float invN,
                                         float2* zf_out, float2* zg_out) {
    float2 E  = make_float2(0.5f * (Zf.x + Zg.x), 0.5f * (Zf.y - Zg.y));
    float2 O  = make_float2(0.5f * (Zf.y + Zg.y), -0.5f * (Zf.x - Zg.x));
    float2 WO = cmul(W, O);
    float2 Xf  = make_float2(E.x + WO.x, E.y + WO.y);
    float2 Xgc = make_float2(E.x - WO.x, E.y - WO.y);      // conj(X[4096-f])
    float2 Pf = cmul(Xf, Af);
    float2 Pg = cmul(make_float2(Xgc.x, -Xgc.y), Ag);
    float2 S  = make_float2(Pf.x + Pg.x, Pf.y - Pg.y);
    float2 Dd = make_float2(Pf.x - Pg.x, Pf.y + Pg.y);
    float2 T1 = cmul(make_float2(W.y, W.x), Dd);
    *zf_out = make_float2(0.5f * invN * (S.x + T1.x), 0.5f * invN * (S.y + T1.y));
    float2 S2 = make_float2(Pg.x + Pf.x, Pg.y - Pf.y);
    float2 D2 = make_float2(Pg.x - Pf.x, Pg.y + Pf.y);
    float2 T2 = cmul(make_float2(W.y, -W.x), D2);
    *zg_out = make_float2(0.5f * invN * (S2.x + T2.x), 0.5f * invN * (S2.y + T2.y));
}

__device__ __forceinline__ void mid_at(float4* s, const float4* Afp, const float4* Agp,
                                       int p, int pq, bool writeg, float invN) {
    int f = rev8_12(p);
    float4 Zf = s[SW(p)];
    float4 Zg = s[SW(pq)];
    float4 Afv = Afp[p];
    float4 Agv = Agp[p];
    float ang = -3.14159265358979323846f * (float)f * (1.0f / 4096.0f);
    float sn, cs; __sincosf(ang, &sn, &cs);
    float2 W = make_float2(cs, sn);
    float2 zf0, zg0, zf1, zg1;
    mid_pair(make_float2(Zf.x, Zf.y), make_float2(Zg.x, Zg.y),
             make_float2(Afv.x, Afv.y), make_float2(Agv.x, Agv.y), W, invN, &zf0, &zg0);
    mid_pair(make_float2(Zf.z, Zf.w), make_float2(Zg.z, Zg.w),
             make_float2(Afv.z, Afv.w), make_float2(Agv.z, Agv.w), W, invN, &zf1, &zg1);
    s[SW(p)] = make_float4(zf0.x, zf0.y, zf1.x, zf1.y);
    if (writeg) s[SW(pq)] = make_float4(zg0.x, zg0.y, zg1.x, zg1.y);
}

// ---------------------------------------------------------------------------
// K0a: basis combine. pa[(h*32+dp)*4096+tt] = packed (a0[2tt],a0[2tt+1],a1[2tt],a1[2tt+1])
// cosv read ONCE (vs 256x before). grid=(16,8), 256 thr.
// ---------------------------------------------------------------------------
__global__ void __launch_bounds__(THREADS)
k_basis(const float* __restrict__ decay, const float* __restrict__ cosv,
        const float* __restrict__ coef) {
    __shared__ float scoef[16 * 64];
    int tid = threadIdx.x;
    int h = blockIdx.y;
    int tt = blockIdx.x * THREADS + tid;
    for (int i = tid; i < 1024; i += THREADS) scoef[i] = coef[h * 1024 + i];
    __syncthreads();
    int t0 = 2 * tt, t1 = 2 * tt + 1;
    const float4* cos4 = (const float4*)cosv;
    float4 r0[4], r1[4];
#pragma unroll
    for (int q = 0; q < 4; ++q) { r0[q] = cos4[t0 * 4 + q]; r1[q] = cos4[t1 * 4 + q]; }
    float de0 = decay[t0], de1 = decay[t1];
    for (int dp = 0; dp < 32; ++dp) {
        int d0 = dp * 2;
        float a00 = 0.f, a10 = 0.f, a01 = 0.f, a11 = 0.f;
#pragma unroll
        for (int kq = 0; kq < 4; ++kq) {
            float4 c0 = r0[kq], c1 = r1[kq];
            float w0 = scoef[(kq * 4 + 0) * 64 + d0], w1 = scoef[(kq * 4 + 1) * 64 + d0];
            float w2 = scoef[(kq * 4 + 2) * 64 + d0], w3 = scoef[(kq * 4 + 3) * 64 + d0];
            float v0 = scoef[(kq * 4 + 0) * 64 + d0 + 1], v1 = scoef[(kq * 4 + 1) * 64 + d0 + 1];
            float v2 = scoef[(kq * 4 + 2) * 64 + d0 + 1], v3 = scoef[(kq * 4 + 3) * 64 + d0 + 1];
            a00 += w0 * c0.x + w1 * c0.y + w2 * c0.z + w3 * c0.w;
            a10 += w0 * c1.x + w1 * c1.y + w2 * c1.z + w3 * c1.w;
            a01 += v0 * c0.x + v1 * c0.y + v2 * c0.z + v3 * c0.w;
            a11 += v0 * c1.x + v1 * c1.y + v2 * c1.z + v3 * c1.w;
        }
        g_pa[(size_t)(h * 32 + dp) * 4096 + tt] =
            make_float4(a00 * de0, a10 * de1, a01 * de0, a11 * de1);
    }
}

// ---------------------------------------------------------------------------
// K0b: FFT the filter; store full-DFT spectrum values in digit-reversed layout.
// grid=(32 dpairs, 8 h), 256 thr.
// ---------------------------------------------------------------------------
__global__ void __launch_bounds__(THREADS)
k_fft_filter() {
    extern __shared__ float4 s[];
    int tid = threadIdx.x;
    int dp = blockIdx.x, h = blockIdx.y;
    size_t off = (size_t)(h * 32 + dp) * 4096;
    for (int i = 0; i < 16; ++i) {
        int t = tid + (i << 8);
        s[SW(t)] = g_pa[off + t];
    }
    __syncthreads();
    fft8_fwd(s, tid);

    float4* Afp = g_Af + off;
    float4* Agp = g_Ag + off;
    for (int i = 0; i < 16; ++i) {
        int p = tid + (i << 8);
        int f = rev8_12(p);
        int pg = rev8_12((4096 - f) & 4095);
        float4 Zf = s[SW(p)];
        float4 Zg = s[SW(pg)];
        float ang = -3.14159265358979323846f * (float)f * (1.0f / 4096.0f);
        float sn, cs; __sincosf(ang, &sn, &cs);
        float2 W = make_float2(cs, sn);
        // channel 0
        float2 E0  = make_float2(0.5f * (Zf.x + Zg.x), 0.5f * (Zf.y - Zg.y));
        float2 O0  = make_float2(0.5f * (Zf.y + Zg.y), -0.5f * (Zf.x - Zg.x));
        float2 WO0 = cmul(W, O0);
        // channel 1
        float2 E1  = make_float2(0.5f * (Zf.z + Zg.z), 0.5f * (Zf.w - Zg.w));
        float2 O1  = make_float2(0.5f * (Zf.w + Zg.w), -0.5f * (Zf.z - Zg.z));
        float2 WO1 = cmul(W, O1);
        Afp[p] = make_float4(E0.x + WO0.x, E0.y + WO0.y, E1.x + WO1.x, E1.y + WO1.y);
        Agp[p] = make_float4(E0.x - WO0.x, -(E0.y - WO0.y), E1.x - WO1.x, -(E1.y - WO1.y));
    }
}

// ---------------------------------------------------------------------------
// K1: per (b,h,d-pair): pack x -> FFT -> spectrum multiply -> IFFT -> first N.
// grid = (32 d-pairs, 32 bh), 256 thr.
// ---------------------------------------------------------------------------
__global__ void __launch_bounds__(THREADS)
k_conv(const float* __restrict__ x, float* __restrict__ out) {
    extern __shared__ float4 s[];
    int tid = threadIdx.x;
    int dp = blockIdx.x;
    int bh = blockIdx.y;
    int h  = bh & 7;

    const float* xb = x + (size_t)bh * 4096 * 64 + dp * 2;
    for (int i = 0; i < 16; ++i) {
        int t = tid + (i << 8);
        float4 v = make_float4(0.f, 0.f, 0.f, 0.f);
        if (t < 2048) {
            float2 A = *reinterpret_cast<const float2*>(xb + (size_t)(2 * t) * 64);
            float2 B = *reinterpret_cast<const float2*>(xb + (size_t)(2 * t + 1) * 64);
            v = make_float4(A.x, B.x, A.y, B.y);
        }
        s[SW(t)] = v;
    }
    __syncthreads();
    fft8_fwd(s, tid);

    size_t off = (size_t)(h * 32 + dp) * 4096;
    const float4* Afp = g_Af + off;
    const float4* Agp = g_Ag + off;
    const float invN = 1.0f / 4096.0f;
    // Pair-disjoint mid passes (regions proven disjoint; no sync needed between):
    // [512,2304) with partners [2304,4096)
#pragma unroll
    for (int i = 0; i < 7; ++i) {
        int p = 512 + tid + (i << 8);
        int pq = ((8 - (p >> 9)) << 9) | (~p & 511);
        mid_at(s, Afp, Agp, p, pq, true, invN);
    }
    if (tid < 224) {          // [64,288) with partners [288,512)
        int p = 64 + tid;
        int pq = ((8 - (p >> 6)) << 6) | (~p & 63);
        mid_at(s, Afp, Agp, p, pq, true, invN);
    }
    if (tid < 28) {           // [8,36) with partners [36,64)
        int p = 8 + tid;
        int pq = ((8 - (p >> 3)) << 3) | (~p & 7);
        mid_at(s, Afp, Agp, p, pq, true, invN);
    }
    if (tid < 5) {            // [0,5): p=0 and p=4 are self-paired
        int p = tid;
        bool selfp = (p == 0) | (p == 4);
        int pq = selfp ? p : (8 - p);
        mid_at(s, Afp, Agp, p, pq, !selfp, invN);
    }
    __syncthreads();
    fft8_inv(s, tid);

    float* ob = out + (size_t)bh * 4096 * 64 + dp * 2;
    for (int i = 0; i < 8; ++i) {
        int t = tid + (i << 8);
        float4 v = s[SW(t)];
        *reinterpret_cast<float2*>(ob + (size_t)(2 * t) * 64)     = make_float2(v.x, v.z);
        *reinterpret_cast<float2*>(ob + (size_t)(2 * t + 1) * 64) = make_float2(v.y, v.w);
    }
}

extern "C" void kernel_launch(void* const* d_in, const int* in_sizes, int n_in,
                              void* d_out, int out_size) {
    const float* x     = (const float*)d_in[0];
    const float* decay = (const float*)d_in[1];
    const float* cosv  = (const float*)d_in[2];
    const float* coef  = (const float*)d_in[3];
    // d_in[4] = index (arange(N)) -- identity gather of first N samples.
    float* out = (float*)d_out;

    cudaFuncSetAttribute(k_fft_filter, cudaFuncAttributeMaxDynamicSharedMemorySize, 65536);
    cudaFuncSetAttribute(k_conv,       cudaFuncAttributeMaxDynamicSharedMemorySize, 65536);

    k_basis     <<<dim3(16, 8),  THREADS>>>(decay, cosv, coef);
    k_fft_filter<<<dim3(32, 8),  THREADS, 65536>>>();
    k_conv      <<<dim3(32, 32), THREADS, 65536>>>(x, out);
}